// round 10
// baseline (speedup 1.0000x reference)
#include <cuda_runtime.h>
#include <cuda_bf16.h>
#include <cstdint>

#define HW   4096
#define CIN  256
#define CH   128
#define NB   4

// Scratch (__device__ globals; allocation-free rule). ALL natural [f][p] layouts.
__device__ __nv_bfloat16 g_qh[NB*CH*HW], g_ql[NB*CH*HW];  // Q viewed [i=4096][c=128]
__device__ __nv_bfloat16 g_kh[NB*CH*HW], g_kl[NB*CH*HW];  // K natural [c=128][j=4096]
__device__ __nv_bfloat16 g_vh[NB*CH*HW], g_vl[NB*CH*HW];  // V viewed [j=4096][d=128]
__device__ float g_res[NB*CH*HW];                          // res [i][d] flat = [128][4096] view

// ---- bf16 hi/lo split ------------------------------------------------------
__device__ __forceinline__ uint32_t b2u(__nv_bfloat162 v) {
    return *reinterpret_cast<uint32_t*>(&v);
}
__device__ __forceinline__ void bfsplit2(float a, float b,
                                         uint32_t& hi, uint32_t& lo) {
    __nv_bfloat162 h = __floats2bfloat162_rn(a, b);
    float ra = a - __low2float(h);
    float rb = b - __high2float(h);
    __nv_bfloat162 l = __floats2bfloat162_rn(ra, rb);
    hi = b2u(h); lo = b2u(l);
}

__device__ __forceinline__ uint32_t smem_u32(const void* p) {
    uint32_t a;
    asm("{ .reg .u64 t; cvta.to.shared.u64 t, %1; cvt.u32.u64 %0, t; }"
        : "=r"(a) : "l"(p));
    return a;
}

// ---- mma.sync / ldmatrix / cp.async wrappers (portable sm_80+) -------------
__device__ __forceinline__ void ldsm4(uint32_t* r, uint32_t addr) {
    asm volatile("ldmatrix.sync.aligned.m8n8.x4.shared.b16 {%0,%1,%2,%3}, [%4];"
                 : "=r"(r[0]), "=r"(r[1]), "=r"(r[2]), "=r"(r[3]) : "r"(addr));
}
__device__ __forceinline__ void ldsm4t(uint32_t* r, uint32_t addr) {
    asm volatile("ldmatrix.sync.aligned.m8n8.x4.trans.shared.b16 {%0,%1,%2,%3}, [%4];"
                 : "=r"(r[0]), "=r"(r[1]), "=r"(r[2]), "=r"(r[3]) : "r"(addr));
}
__device__ __forceinline__ void mma16816(float* d, const uint32_t* a,
                                         uint32_t b0, uint32_t b1) {
    asm volatile(
        "mma.sync.aligned.m16n8k16.row.col.f32.bf16.bf16.f32 "
        "{%0,%1,%2,%3}, {%4,%5,%6,%7}, {%8,%9}, {%0,%1,%2,%3};"
        : "+f"(d[0]), "+f"(d[1]), "+f"(d[2]), "+f"(d[3])
        : "r"(a[0]), "r"(a[1]), "r"(a[2]), "r"(a[3]), "r"(b0), "r"(b1));
}
__device__ __forceinline__ void cpasync16(uint32_t dst, const void* src) {
    asm volatile("cp.async.cg.shared.global [%0], [%1], 16;" :: "r"(dst), "l"(src));
}
#define CP_COMMIT() asm volatile("cp.async.commit_group;" ::: "memory")
#define CP_WAIT1()  asm volatile("cp.async.wait_group 1;" ::: "memory")
#define CP_WAIT0()  asm volatile("cp.async.wait_group 0;" ::: "memory")

// ---- swizzled smem offsets (16B chunk XOR by row) --------------------------
__device__ __forceinline__ uint32_t off256(int r, int c) {  // 256B rows, 128 bf16 cols
    return (uint32_t)(r * 256 + ((((c >> 3) ^ r) & 7) << 4) + ((c >> 3) & ~7) * 16 + (c & 7) * 2);
}
__device__ __forceinline__ uint32_t off128b(int r, int c) { // 128B rows, 64 bf16 cols
    return (uint32_t)(r * 128 + (((c >> 3) ^ (r & 7)) << 4) + (c & 7) * 2);
}

// ---------------------------------------------------------------------------
// Kernel 1: QKV via mma.sync bf16x3. 512 thr: 16 warps = 8(m) x 2(n-half).
// ---------------------------------------------------------------------------
#define QS_XH 0            // X: [256 k][128 n] bf16
#define QS_XL 65536
#define QS_WH 131072       // W half: [128 m][128 k] bf16
#define QS_WL 163840
#define QKV_SMEM 196608    // 192 KB

__global__ __launch_bounds__(512, 1) void qkv_mma(
        const float* __restrict__ x,
        const float* __restrict__ w1,
        const float* __restrict__ w2,
        const float* __restrict__ w3) {
    extern __shared__ char sm[];
    const uint32_t smb = smem_u32(sm);
    const int tid = threadIdx.x, lane = tid & 31, wid = tid >> 5;
    const int lr = lane & 15, lk = (lane >> 4) * 8;
    const int qr = lane >> 2, qc = (lane & 3) * 2;
    const int wm = wid & 7, wn = wid >> 3;
    const int m0 = wm * 16;
    const int b = blockIdx.y, p0 = blockIdx.x * 128;
    const float* X = x + (size_t)b * CIN * HW;
    const size_t bo = (size_t)b * CH * HW;

    // ---- split X tile [256][128] fp32 -> bf16 hi/lo smem (once) ----
#pragma unroll 4
    for (int i = tid; i < 256 * 32; i += 512) {
        int r = i >> 5, c4 = (i & 31) * 4;
        float4 v = *(const float4*)&X[(size_t)r * HW + p0 + c4];
        uint32_t h0, l0, h1, l1;
        bfsplit2(v.x, v.y, h0, l0);
        bfsplit2(v.z, v.w, h1, l1);
        uint32_t o = off256(r, c4);
        *(uint32_t*)(sm + QS_XH + o) = h0;
        *(uint32_t*)(sm + QS_XL + o) = l0;
        *(uint32_t*)(sm + QS_XH + o + 4) = h1;
        *(uint32_t*)(sm + QS_XL + o + 4) = l1;
    }
    __syncthreads();

#pragma unroll 1
    for (int s = 0; s < 3; s++) {
        const float* W = (s == 0) ? w1 : (s == 1) ? w2 : w3;
        __nv_bfloat16* OH = ((s == 0) ? g_qh : (s == 1) ? g_kh : g_vh) + bo;
        __nv_bfloat16* OL = ((s == 0) ? g_ql : (s == 1) ? g_kl : g_vl) + bo;

        float acc[8][4];
#pragma unroll
        for (int n = 0; n < 8; n++)
#pragma unroll
            for (int k = 0; k < 4; k++) acc[n][k] = 0.f;

#pragma unroll 1
        for (int kh = 0; kh < 2; kh++) {
            __syncthreads();
#pragma unroll 2
            for (int i = tid; i < 128 * 32; i += 512) {
                int f = i >> 5, c4 = (i & 31) * 4;
                float4 v = *(const float4*)&W[f * CIN + kh * 128 + c4];
                uint32_t h0, l0, h1, l1;
                bfsplit2(v.x, v.y, h0, l0);
                bfsplit2(v.z, v.w, h1, l1);
                uint32_t o = off256(f, c4);
                *(uint32_t*)(sm + QS_WH + o) = h0;
                *(uint32_t*)(sm + QS_WL + o) = l0;
                *(uint32_t*)(sm + QS_WH + o + 4) = h1;
                *(uint32_t*)(sm + QS_WL + o + 4) = l1;
            }
            __syncthreads();

#pragma unroll
            for (int ks = 0; ks < 8; ks++) {
                uint32_t ah[4], al[4];
                uint32_t aoff = off256(m0 + lr, ks * 16 + lk);
                ldsm4(ah, smb + QS_WH + aoff);
                ldsm4(al, smb + QS_WL + aoff);
#pragma unroll
                for (int jg = 0; jg < 4; jg++) {
                    uint32_t bh[4], bl[4];
                    uint32_t boff = off256(kh * 128 + ks * 16 + lr, wn * 64 + jg * 16 + lk);
                    ldsm4t(bh, smb + QS_XH + boff);
                    ldsm4t(bl, smb + QS_XL + boff);
                    mma16816(acc[jg*2],   ah, bh[0], bh[1]);
                    mma16816(acc[jg*2+1], ah, bh[2], bh[3]);
                    mma16816(acc[jg*2],   ah, bl[0], bl[1]);
                    mma16816(acc[jg*2+1], ah, bl[2], bl[3]);
                    mma16816(acc[jg*2],   al, bh[0], bh[1]);
                    mma16816(acc[jg*2+1], al, bh[2], bh[3]);
                }
            }
        }

        int f1 = m0 + qr;
#pragma unroll
        for (int nb = 0; nb < 8; nb++) {
            int col = p0 + wn * 64 + nb * 8 + qc;
            uint32_t h0, l0, h1, l1;
            bfsplit2(acc[nb][0], acc[nb][1], h0, l0);
            bfsplit2(acc[nb][2], acc[nb][3], h1, l1);
            *(uint32_t*)&OH[(size_t)f1 * HW + col] = h0;
            *(uint32_t*)&OL[(size_t)f1 * HW + col] = l0;
            *(uint32_t*)&OH[(size_t)(f1 + 8) * HW + col] = h1;
            *(uint32_t*)&OL[(size_t)(f1 + 8) * HW + col] = l1;
        }
    }
}

// ---------------------------------------------------------------------------
// Kernel 2: flash attention. 512 thr: 16 warps = 8(m) x 2(j-half).
// Each warp: S over j32, exp, partial O over its j-half; one end reduction.
// ---------------------------------------------------------------------------
#define SQH 0
#define SQL 32768
#define SST 65536
#define KHO 0
#define KLO 16384
#define VHO 32768
#define VLO 49152
#define STAGE 65536
#define FLASH_SMEM (SST + 2 * STAGE)   // 192 KB
// end-of-kernel reduction areas (alias stage buffers)
#define RED_O  SST
#define RED_L  (SST + 65536)

__global__ __launch_bounds__(512, 1) void flash_mma() {
    extern __shared__ char sm[];
    const uint32_t smb = smem_u32(sm);
    const int tid = threadIdx.x, lane = tid & 31, wid = tid >> 5;
    const int lr = lane & 15, lk = (lane >> 4) * 8;
    const int wm = wid & 7, wn = wid >> 3;
    const int m0 = wm * 16, jb = wn * 32;
    const int b = blockIdx.y, i0 = blockIdx.x * 128;
    const size_t bo = (size_t)b * CH * HW;
    const __nv_bfloat16 *Qh = g_qh + bo, *Ql = g_ql + bo;
    const __nv_bfloat16 *Kh = g_kh + bo, *Kl = g_kl + bo;
    const __nv_bfloat16 *Vh = g_vh + bo, *Vl = g_vl + bo;

#pragma unroll 2
    for (int i = tid; i < 2048; i += 512) {
        int r = i >> 4, c8 = (i & 15) * 8;
        uint32_t off = off256(r, c8);
        *(uint4*)(sm + SQH + off) = *(const uint4*)(Qh + (size_t)(i0 + r) * 128 + c8);
        *(uint4*)(sm + SQL + off) = *(const uint4*)(Ql + (size_t)(i0 + r) * 128 + c8);
    }

    auto prefetch = [&](int tt, int stg) {
        const int j0 = tt * 64;
        const uint32_t base = smb + SST + (uint32_t)stg * STAGE;
#pragma unroll
        for (int q = 0; q < 2; q++) {
            int i = tid + q * 512;
            {
                int c = i >> 3, j8 = (i & 7) * 8;
                uint32_t o = off128b(c, j8);
                cpasync16(base + KHO + o, Kh + (size_t)c * HW + j0 + j8);
                cpasync16(base + KLO + o, Kl + (size_t)c * HW + j0 + j8);
            }
            {
                int j = i >> 4, d8 = (i & 15) * 8;
                uint32_t o = off256(j, d8);
                cpasync16(base + VHO + o, Vh + (size_t)(j0 + j) * 128 + d8);
                cpasync16(base + VLO + o, Vl + (size_t)(j0 + j) * 128 + d8);
            }
        }
    };

    prefetch(0, 0);
    CP_COMMIT();

    float O[16][4];
#pragma unroll
    for (int d = 0; d < 16; d++)
#pragma unroll
        for (int k = 0; k < 4; k++) O[d][k] = 0.f;
    float ls0 = 0.f, ls1 = 0.f;

    for (int t = 0; t < 64; t++) {
        if (t < 63) { prefetch(t + 1, (t + 1) & 1); CP_COMMIT(); CP_WAIT1(); }
        else        { CP_WAIT0(); }
        __syncthreads();
        const uint32_t kb = smb + SST + (uint32_t)(t & 1) * STAGE;

        // ---- S over my j32 half ----
        float S[4][4];
#pragma unroll
        for (int n = 0; n < 4; n++)
#pragma unroll
            for (int k = 0; k < 4; k++) S[n][k] = 0.f;

#pragma unroll
        for (int ks = 0; ks < 8; ks++) {
            uint32_t qh[4], ql[4];
            uint32_t qoff = off256(m0 + lr, ks * 16 + lk);
            ldsm4(qh, smb + SQH + qoff);
            ldsm4(ql, smb + SQL + qoff);
#pragma unroll
            for (int jg = 0; jg < 2; jg++) {
                uint32_t khf[4], klf[4];
                uint32_t koff = off128b(ks * 16 + lr, jb + jg * 16 + lk);
                ldsm4t(khf, kb + KHO + koff);
                ldsm4t(klf, kb + KLO + koff);
                mma16816(S[jg*2],   qh, khf[0], khf[1]);
                mma16816(S[jg*2+1], qh, khf[2], khf[3]);
                mma16816(S[jg*2],   qh, klf[0], klf[1]);
                mma16816(S[jg*2+1], qh, klf[2], klf[3]);
                mma16816(S[jg*2],   ql, khf[0], khf[1]);
                mma16816(S[jg*2+1], ql, khf[2], khf[3]);
            }
        }

        // ---- exp + in-register P + partial row sums ----
        uint32_t pH[2][4], pL[2][4];
        float a0 = 0.f, a1 = 0.f;
#pragma unroll
        for (int nb = 0; nb < 4; nb++) {
            float e0 = __expf(S[nb][0]), e1 = __expf(S[nb][1]);
            float e2 = __expf(S[nb][2]), e3 = __expf(S[nb][3]);
            a0 += e0 + e1; a1 += e2 + e3;
            int kbi = nb >> 1, hf = (nb & 1) * 2;
            bfsplit2(e0, e1, pH[kbi][hf],     pL[kbi][hf]);
            bfsplit2(e2, e3, pH[kbi][hf + 1], pL[kbi][hf + 1]);
        }
        a0 += __shfl_xor_sync(0xffffffffu, a0, 1);
        a0 += __shfl_xor_sync(0xffffffffu, a0, 2);
        a1 += __shfl_xor_sync(0xffffffffu, a1, 1);
        a1 += __shfl_xor_sync(0xffffffffu, a1, 2);
        ls0 += a0; ls1 += a1;

        // ---- partial O += P V over my j32 ----
#pragma unroll
        for (int kbi = 0; kbi < 2; kbi++) {
#pragma unroll
            for (int dg = 0; dg < 8; dg++) {
                uint32_t vhf[4], vlf[4];
                uint32_t voff = off256(jb + kbi * 16 + lr, dg * 16 + lk);
                ldsm4t(vhf, kb + VHO + voff);
                ldsm4t(vlf, kb + VLO + voff);
                mma16816(O[dg*2],   pH[kbi], vhf[0], vhf[1]);
                mma16816(O[dg*2+1], pH[kbi], vhf[2], vhf[3]);
                mma16816(O[dg*2],   pH[kbi], vlf[0], vlf[1]);
                mma16816(O[dg*2+1], pH[kbi], vlf[2], vlf[3]);
                mma16816(O[dg*2],   pL[kbi], vhf[0], vhf[1]);
                mma16816(O[dg*2+1], pL[kbi], vhf[2], vhf[3]);
            }
        }
        __syncthreads();
    }

    // ---- cross-half reduction (once): wn==1 dumps partials, wn==0 combines --
    if (wn == 1) {
        float* ro = (float*)(sm + RED_O) + (size_t)(wm * 32 + lane) * 64;
#pragma unroll
        for (int db = 0; db < 16; db++)
            *(float4*)(ro + db * 4) = make_float4(O[db][0], O[db][1], O[db][2], O[db][3]);
        float* rl = (float*)(sm + RED_L) + (wm * 32 + lane) * 2;
        rl[0] = ls0; rl[1] = ls1;
    }
    __syncthreads();
    if (wn == 0) {
        const float* ro = (const float*)(sm + RED_O) + (size_t)(wm * 32 + lane) * 64;
        const float* rl = (const float*)(sm + RED_L) + (wm * 32 + lane) * 2;
        float inv0 = 1.0f / (ls0 + rl[0]);
        float inv1 = 1.0f / (ls1 + rl[1]);
        int r1 = i0 + m0 + (lane >> 2), r2 = r1 + 8;
        float* R = g_res + bo;
#pragma unroll
        for (int db = 0; db < 16; db++) {
            float4 p = *(const float4*)(ro + db * 4);
            int d = db * 8 + (lane & 3) * 2;
            *(float2*)&R[(size_t)r1 * 128 + d] =
                make_float2((O[db][0] + p.x) * inv0, (O[db][1] + p.y) * inv0);
            *(float2*)&R[(size_t)r2 * 128 + d] =
                make_float2((O[db][2] + p.z) * inv1, (O[db][3] + p.w) * inv1);
        }
    }
}

// ---------------------------------------------------------------------------
// Kernel 3: out = BN(w4 @ res_view) + x. 512 thr: 16 warps, one m16 each.
// ---------------------------------------------------------------------------
#define OS_RH 0            // res: [128 c][128 p] bf16
#define OS_RL 32768
#define OS_WH 65536        // w4: [256 o][128 c] bf16
#define OS_WL 131072
#define OUT_SMEM 196608    // 192 KB

__global__ __launch_bounds__(512, 1) void out_mma(
        const float* __restrict__ x,
        const float* __restrict__ w4,
        const float* __restrict__ gamma,
        const float* __restrict__ beta,
        const float* __restrict__ rmean,
        const float* __restrict__ rvar,
        float* __restrict__ out) {
    extern __shared__ char sm[];
    const uint32_t smb = smem_u32(sm);
    const int tid = threadIdx.x, lane = tid & 31, wid = tid >> 5;
    const int lr = lane & 15, lk = (lane >> 4) * 8;
    const int qr = lane >> 2, qc = (lane & 3) * 2;
    const int m0 = wid * 16;
    const int b = blockIdx.y, p0 = blockIdx.x * 128;
    const float* R = g_res + (size_t)b * CH * HW;

#pragma unroll 2
    for (int i = tid; i < 128 * 32; i += 512) {
        int c = i >> 5, p4 = (i & 31) * 4;
        float4 v = *(const float4*)&R[(size_t)c * HW + p0 + p4];
        uint32_t h0, l0, h1, l1;
        bfsplit2(v.x, v.y, h0, l0);
        bfsplit2(v.z, v.w, h1, l1);
        uint32_t o = off256(c, p4);
        *(uint32_t*)(sm + OS_RH + o) = h0;
        *(uint32_t*)(sm + OS_RL + o) = l0;
        *(uint32_t*)(sm + OS_RH + o + 4) = h1;
        *(uint32_t*)(sm + OS_RL + o + 4) = l1;
    }
#pragma unroll 4
    for (int i = tid; i < 256 * 32; i += 512) {
        int oo = i >> 5, c4 = (i & 31) * 4;
        float4 v = *(const float4*)&w4[oo * CH + c4];
        uint32_t h0, l0, h1, l1;
        bfsplit2(v.x, v.y, h0, l0);
        bfsplit2(v.z, v.w, h1, l1);
        uint32_t o = off256(oo, c4);
        *(uint32_t*)(sm + OS_WH + o) = h0;
        *(uint32_t*)(sm + OS_WL + o) = l0;
        *(uint32_t*)(sm + OS_WH + o + 4) = h1;
        *(uint32_t*)(sm + OS_WL + o + 4) = l1;
    }
    __syncthreads();

    float acc[16][4];
#pragma unroll
    for (int n = 0; n < 16; n++)
#pragma unroll
        for (int k = 0; k < 4; k++) acc[n][k] = 0.f;

#pragma unroll
    for (int ks = 0; ks < 8; ks++) {
        uint32_t ah[4], al[4];
        uint32_t aoff = off256(m0 + lr, ks * 16 + lk);
        ldsm4(ah, smb + OS_WH + aoff);
        ldsm4(al, smb + OS_WL + aoff);
#pragma unroll
        for (int jg = 0; jg < 8; jg++) {
            uint32_t bh[4], bl[4];
            uint32_t boff = off256(ks * 16 + lr, jg * 16 + lk);
            ldsm4t(bh, smb + OS_RH + boff);
            ldsm4t(bl, smb + OS_RL + boff);
            mma16816(acc[jg*2],   ah, bh[0], bh[1]);
            mma16816(acc[jg*2+1], ah, bh[2], bh[3]);
            mma16816(acc[jg*2],   ah, bl[0], bl[1]);
            mma16816(acc[jg*2+1], ah, bl[2], bl[3]);
            mma16816(acc[jg*2],   al, bh[0], bh[1]);
            mma16816(acc[jg*2+1], al, bh[2], bh[3]);
        }
    }

    int oc1 = m0 + qr, oc2 = oc1 + 8;
    float sc1 = gamma[oc1] * rsqrtf(rvar[oc1] + 1e-5f);
    float sc2 = gamma[oc2] * rsqrtf(rvar[oc2] + 1e-5f);
    float mu1 = rmean[oc1], bt1 = beta[oc1];
    float mu2 = rmean[oc2], bt2 = beta[oc2];
    size_t b1 = (size_t)b * CIN * HW + (size_t)oc1 * HW + p0;
    size_t b2 = (size_t)b * CIN * HW + (size_t)oc2 * HW + p0;
#pragma unroll
    for (int nb = 0; nb < 16; nb++) {
        int col = nb * 8 + qc;
        float2 xv1 = *(const float2*)&x[b1 + col];
        float2 xv2 = *(const float2*)&x[b2 + col];
        *(float2*)&out[b1 + col] = make_float2((acc[nb][0] - mu1) * sc1 + bt1 + xv1.x,
                                               (acc[nb][1] - mu1) * sc1 + bt1 + xv1.y);
        *(float2*)&out[b2 + col] = make_float2((acc[nb][2] - mu2) * sc2 + bt2 + xv2.x,
                                               (acc[nb][3] - mu2) * sc2 + bt2 + xv2.y);
    }
}

// ---------------------------------------------------------------------------
extern "C" void kernel_launch(void* const* d_in, const int* in_sizes, int n_in,
                              void* d_out, int out_size) {
    const float* x     = (const float*)d_in[0];
    const float* w1    = (const float*)d_in[1];
    const float* w2    = (const float*)d_in[2];
    const float* w3    = (const float*)d_in[3];
    const float* w4    = (const float*)d_in[4];
    const float* gamma = (const float*)d_in[5];
    const float* beta  = (const float*)d_in[6];
    const float* rmean = (const float*)d_in[7];
    const float* rvar  = (const float*)d_in[8];
    float* out = (float*)d_out;

    cudaFuncSetAttribute(qkv_mma,
                         cudaFuncAttributeMaxDynamicSharedMemorySize, QKV_SMEM);
    qkv_mma<<<dim3(32, NB), 512, QKV_SMEM>>>(x, w1, w2, w3);

    cudaFuncSetAttribute(flash_mma,
                         cudaFuncAttributeMaxDynamicSharedMemorySize, FLASH_SMEM);
    flash_mma<<<dim3(32, NB), 512, FLASH_SMEM>>>();

    cudaFuncSetAttribute(out_mma,
                         cudaFuncAttributeMaxDynamicSharedMemorySize, OUT_SMEM);
    out_mma<<<dim3(32, NB), 512, OUT_SMEM>>>(x, w4, gamma, beta, rmean, rvar, out);
}

// round 11
// speedup vs baseline: 1.0685x; 1.0685x over previous
#include <cuda_runtime.h>
#include <cuda_bf16.h>
#include <cstdint>

#define HW   4096
#define CIN  256
#define CH   128
#define NB   4

// Scratch (__device__ globals; allocation-free rule). ALL natural [f][p] layouts.
__device__ __nv_bfloat16 g_qh[NB*CH*HW], g_ql[NB*CH*HW];  // Q viewed [i=4096][c=128]
__device__ __nv_bfloat16 g_kh[NB*CH*HW], g_kl[NB*CH*HW];  // K natural [c=128][j=4096]
__device__ __nv_bfloat16 g_vh[NB*CH*HW], g_vl[NB*CH*HW];  // V viewed [j=4096][d=128]
__device__ float g_res[NB*CH*HW];                          // res [i][d] flat = [128][4096] view

// ---- bf16 hi/lo split ------------------------------------------------------
__device__ __forceinline__ uint32_t b2u(__nv_bfloat162 v) {
    return *reinterpret_cast<uint32_t*>(&v);
}
__device__ __forceinline__ void bfsplit2(float a, float b,
                                         uint32_t& hi, uint32_t& lo) {
    __nv_bfloat162 h = __floats2bfloat162_rn(a, b);
    float ra = a - __low2float(h);
    float rb = b - __high2float(h);
    __nv_bfloat162 l = __floats2bfloat162_rn(ra, rb);
    hi = b2u(h); lo = b2u(l);
}

__device__ __forceinline__ uint32_t smem_u32(const void* p) {
    uint32_t a;
    asm("{ .reg .u64 t; cvta.to.shared.u64 t, %1; cvt.u32.u64 %0, t; }"
        : "=r"(a) : "l"(p));
    return a;
}

// ---- mma.sync / ldmatrix / cp.async wrappers (portable sm_80+) -------------
__device__ __forceinline__ void ldsm4(uint32_t* r, uint32_t addr) {
    asm volatile("ldmatrix.sync.aligned.m8n8.x4.shared.b16 {%0,%1,%2,%3}, [%4];"
                 : "=r"(r[0]), "=r"(r[1]), "=r"(r[2]), "=r"(r[3]) : "r"(addr));
}
__device__ __forceinline__ void ldsm4t(uint32_t* r, uint32_t addr) {
    asm volatile("ldmatrix.sync.aligned.m8n8.x4.trans.shared.b16 {%0,%1,%2,%3}, [%4];"
                 : "=r"(r[0]), "=r"(r[1]), "=r"(r[2]), "=r"(r[3]) : "r"(addr));
}
__device__ __forceinline__ void mma16816(float* d, const uint32_t* a,
                                         uint32_t b0, uint32_t b1) {
    asm volatile(
        "mma.sync.aligned.m16n8k16.row.col.f32.bf16.bf16.f32 "
        "{%0,%1,%2,%3}, {%4,%5,%6,%7}, {%8,%9}, {%0,%1,%2,%3};"
        : "+f"(d[0]), "+f"(d[1]), "+f"(d[2]), "+f"(d[3])
        : "r"(a[0]), "r"(a[1]), "r"(a[2]), "r"(a[3]), "r"(b0), "r"(b1));
}
__device__ __forceinline__ void cpasync16(uint32_t dst, const void* src) {
    asm volatile("cp.async.cg.shared.global [%0], [%1], 16;" :: "r"(dst), "l"(src));
}
#define CP_COMMIT() asm volatile("cp.async.commit_group;" ::: "memory")
#define CP_WAIT1()  asm volatile("cp.async.wait_group 1;" ::: "memory")
#define CP_WAIT0()  asm volatile("cp.async.wait_group 0;" ::: "memory")

// ---- swizzled smem offsets (16B chunk XOR by row) --------------------------
__device__ __forceinline__ uint32_t off256(int r, int c) {  // 256B rows, 128 bf16 cols
    return (uint32_t)(r * 256 + ((((c >> 3) ^ r) & 7) << 4) + ((c >> 3) & ~7) * 16 + (c & 7) * 2);
}
__device__ __forceinline__ uint32_t off128b(int r, int c) { // 128B rows, 64 bf16 cols
    return (uint32_t)(r * 128 + (((c >> 3) ^ (r & 7)) << 4) + (c & 7) * 2);
}

// ---------------------------------------------------------------------------
// Kernel 1: QKV via mma.sync bf16x3. 512 thr: 16 warps = 8(m) x 2(n-half).
// W A-fragments loaded DIRECTLY from global (no W smem, no per-half syncs).
// ---------------------------------------------------------------------------
#define QS_XH 0            // X: [256 k][128 n] bf16
#define QS_XL 65536
#define QKV_SMEM 131072    // 128 KB

__global__ __launch_bounds__(512, 1) void qkv_mma(
        const float* __restrict__ x,
        const float* __restrict__ w1,
        const float* __restrict__ w2,
        const float* __restrict__ w3) {
    extern __shared__ char sm[];
    const uint32_t smb = smem_u32(sm);
    const int tid = threadIdx.x, lane = tid & 31, wid = tid >> 5;
    const int lr = lane & 15, lk = (lane >> 4) * 8;
    const int qr = lane >> 2, qc = (lane & 3) * 2;
    const int wm = wid & 7, wn = wid >> 3;
    const int m0 = wm * 16;
    const int b = blockIdx.y, p0 = blockIdx.x * 128;
    const float* X = x + (size_t)b * CIN * HW;
    const size_t bo = (size_t)b * CH * HW;

    // ---- split X tile [256][128] fp32 -> bf16 hi/lo smem (once) ----
#pragma unroll 4
    for (int i = tid; i < 256 * 32; i += 512) {
        int r = i >> 5, c4 = (i & 31) * 4;
        float4 v = *(const float4*)&X[(size_t)r * HW + p0 + c4];
        uint32_t h0, l0, h1, l1;
        bfsplit2(v.x, v.y, h0, l0);
        bfsplit2(v.z, v.w, h1, l1);
        uint32_t o = off256(r, c4);
        *(uint32_t*)(sm + QS_XH + o) = h0;
        *(uint32_t*)(sm + QS_XL + o) = l0;
        *(uint32_t*)(sm + QS_XH + o + 4) = h1;
        *(uint32_t*)(sm + QS_XL + o + 4) = l1;
    }
    __syncthreads();

    // my A-fragment global offsets (rows m0+qr / m0+qr+8, col pairs qc / qc+8)
    const int ra = (m0 + qr) * CIN, rb = (m0 + qr + 8) * CIN;

#pragma unroll 1
    for (int s = 0; s < 3; s++) {
        const float* W = (s == 0) ? w1 : (s == 1) ? w2 : w3;
        __nv_bfloat16* OH = ((s == 0) ? g_qh : (s == 1) ? g_kh : g_vh) + bo;
        __nv_bfloat16* OL = ((s == 0) ? g_ql : (s == 1) ? g_kl : g_vl) + bo;

        float acc[8][4];
#pragma unroll
        for (int n = 0; n < 8; n++)
#pragma unroll
            for (int k = 0; k < 4; k++) acc[n][k] = 0.f;

#pragma unroll
        for (int ks = 0; ks < 16; ks++) {
            const int c0 = ks * 16 + qc;
            float2 wv0 = *(const float2*)&W[ra + c0];
            float2 wv1 = *(const float2*)&W[rb + c0];
            float2 wv2 = *(const float2*)&W[ra + c0 + 8];
            float2 wv3 = *(const float2*)&W[rb + c0 + 8];
            uint32_t ah[4], al[4];
            bfsplit2(wv0.x, wv0.y, ah[0], al[0]);
            bfsplit2(wv1.x, wv1.y, ah[1], al[1]);
            bfsplit2(wv2.x, wv2.y, ah[2], al[2]);
            bfsplit2(wv3.x, wv3.y, ah[3], al[3]);
#pragma unroll
            for (int jg = 0; jg < 4; jg++) {
                uint32_t bh[4], bl[4];
                uint32_t boff = off256(ks * 16 + lr, wn * 64 + jg * 16 + lk);
                ldsm4t(bh, smb + QS_XH + boff);
                ldsm4t(bl, smb + QS_XL + boff);
                mma16816(acc[jg*2],   ah, bh[0], bh[1]);
                mma16816(acc[jg*2+1], ah, bh[2], bh[3]);
                mma16816(acc[jg*2],   ah, bl[0], bl[1]);
                mma16816(acc[jg*2+1], ah, bl[2], bl[3]);
                mma16816(acc[jg*2],   al, bh[0], bh[1]);
                mma16816(acc[jg*2+1], al, bh[2], bh[3]);
            }
        }

        int f1 = m0 + qr;
#pragma unroll
        for (int nb = 0; nb < 8; nb++) {
            int col = p0 + wn * 64 + nb * 8 + qc;
            uint32_t h0, l0, h1, l1;
            bfsplit2(acc[nb][0], acc[nb][1], h0, l0);
            bfsplit2(acc[nb][2], acc[nb][3], h1, l1);
            *(uint32_t*)&OH[(size_t)f1 * HW + col] = h0;
            *(uint32_t*)&OL[(size_t)f1 * HW + col] = l0;
            *(uint32_t*)&OH[(size_t)(f1 + 8) * HW + col] = h1;
            *(uint32_t*)&OL[(size_t)(f1 + 8) * HW + col] = l1;
        }
    }
}

// ---------------------------------------------------------------------------
// Kernel 2: FA2-style flash attention (round-8 256-thread version, verbatim).
// ---------------------------------------------------------------------------
#define SQH 0
#define SQL 32768
#define SST 65536
#define KHO 0
#define KLO 16384
#define VHO 32768
#define VLO 49152
#define STAGE 65536
#define FLASH_SMEM (SST + 2 * STAGE)   // 192 KB

__global__ __launch_bounds__(256, 1) void flash_mma() {
    extern __shared__ char sm[];
    const uint32_t smb = smem_u32(sm);
    const int tid = threadIdx.x, lane = tid & 31, wid = tid >> 5;
    const int lr = lane & 15, lk = (lane >> 4) * 8;
    const int m0 = wid * 16;
    const int b = blockIdx.y, i0 = blockIdx.x * 128;
    const size_t bo = (size_t)b * CH * HW;
    const __nv_bfloat16 *Qh = g_qh + bo, *Ql = g_ql + bo;
    const __nv_bfloat16 *Kh = g_kh + bo, *Kl = g_kl + bo;
    const __nv_bfloat16 *Vh = g_vh + bo, *Vl = g_vl + bo;

#pragma unroll 4
    for (int i = tid; i < 2048; i += 256) {
        int r = i >> 4, c8 = (i & 15) * 8;
        uint32_t off = off256(r, c8);
        *(uint4*)(sm + SQH + off) = *(const uint4*)(Qh + (size_t)(i0 + r) * 128 + c8);
        *(uint4*)(sm + SQL + off) = *(const uint4*)(Ql + (size_t)(i0 + r) * 128 + c8);
    }

    auto prefetch = [&](int tt, int stg) {
        const int j0 = tt * 64;
        const uint32_t base = smb + SST + (uint32_t)stg * STAGE;
#pragma unroll
        for (int q = 0; q < 4; q++) {
            int i = tid + q * 256;
            {
                int c = i >> 3, j8 = (i & 7) * 8;
                uint32_t o = off128b(c, j8);
                cpasync16(base + KHO + o, Kh + (size_t)c * HW + j0 + j8);
                cpasync16(base + KLO + o, Kl + (size_t)c * HW + j0 + j8);
            }
            {
                int j = i >> 4, d8 = (i & 15) * 8;
                uint32_t o = off256(j, d8);
                cpasync16(base + VHO + o, Vh + (size_t)(j0 + j) * 128 + d8);
                cpasync16(base + VLO + o, Vl + (size_t)(j0 + j) * 128 + d8);
            }
        }
    };

    prefetch(0, 0);
    CP_COMMIT();

    float O[16][4];
#pragma unroll
    for (int d = 0; d < 16; d++)
#pragma unroll
        for (int k = 0; k < 4; k++) O[d][k] = 0.f;
    float ls0 = 0.f, ls1 = 0.f;

    for (int t = 0; t < 64; t++) {
        if (t < 63) { prefetch(t + 1, (t + 1) & 1); CP_COMMIT(); CP_WAIT1(); }
        else        { CP_WAIT0(); }
        __syncthreads();
        const uint32_t kb = smb + SST + (uint32_t)(t & 1) * STAGE;

        float S[8][4];
#pragma unroll
        for (int n = 0; n < 8; n++)
#pragma unroll
            for (int k = 0; k < 4; k++) S[n][k] = 0.f;

#pragma unroll
        for (int ks = 0; ks < 8; ks++) {
            uint32_t qh[4], ql[4];
            uint32_t qoff = off256(m0 + lr, ks * 16 + lk);
            ldsm4(qh, smb + SQH + qoff);
            ldsm4(ql, smb + SQL + qoff);
#pragma unroll
            for (int jg = 0; jg < 4; jg++) {
                uint32_t khf[4], klf[4];
                uint32_t koff = off128b(ks * 16 + lr, jg * 16 + lk);
                ldsm4t(khf, kb + KHO + koff);
                ldsm4t(klf, kb + KLO + koff);
                mma16816(S[jg*2],   qh, khf[0], khf[1]);
                mma16816(S[jg*2+1], qh, khf[2], khf[3]);
                mma16816(S[jg*2],   qh, klf[0], klf[1]);
                mma16816(S[jg*2+1], qh, klf[2], klf[3]);
                mma16816(S[jg*2],   ql, khf[0], khf[1]);
                mma16816(S[jg*2+1], ql, khf[2], khf[3]);
            }
        }

        uint32_t pH[4][4], pL[4][4];
        float a0 = 0.f, a1 = 0.f;
#pragma unroll
        for (int nb = 0; nb < 8; nb++) {
            float e0 = __expf(S[nb][0]), e1 = __expf(S[nb][1]);
            float e2 = __expf(S[nb][2]), e3 = __expf(S[nb][3]);
            a0 += e0 + e1; a1 += e2 + e3;
            int kbi = nb >> 1, hf = (nb & 1) * 2;
            bfsplit2(e0, e1, pH[kbi][hf],     pL[kbi][hf]);
            bfsplit2(e2, e3, pH[kbi][hf + 1], pL[kbi][hf + 1]);
        }
        a0 += __shfl_xor_sync(0xffffffffu, a0, 1);
        a0 += __shfl_xor_sync(0xffffffffu, a0, 2);
        a1 += __shfl_xor_sync(0xffffffffu, a1, 1);
        a1 += __shfl_xor_sync(0xffffffffu, a1, 2);
        ls0 += a0; ls1 += a1;

#pragma unroll
        for (int kbi = 0; kbi < 4; kbi++) {
#pragma unroll
            for (int dg = 0; dg < 8; dg++) {
                uint32_t vhf[4], vlf[4];
                uint32_t voff = off256(kbi * 16 + lr, dg * 16 + lk);
                ldsm4t(vhf, kb + VHO + voff);
                ldsm4t(vlf, kb + VLO + voff);
                mma16816(O[dg*2],   pH[kbi], vhf[0], vhf[1]);
                mma16816(O[dg*2+1], pH[kbi], vhf[2], vhf[3]);
                mma16816(O[dg*2],   pH[kbi], vlf[0], vlf[1]);
                mma16816(O[dg*2+1], pH[kbi], vlf[2], vlf[3]);
                mma16816(O[dg*2],   pL[kbi], vhf[0], vhf[1]);
                mma16816(O[dg*2+1], pL[kbi], vhf[2], vhf[3]);
            }
        }
        __syncthreads();
    }

    float inv0 = 1.0f / ls0, inv1 = 1.0f / ls1;
    int r1 = i0 + m0 + (lane >> 2), r2 = r1 + 8;
    float* R = g_res + bo;
#pragma unroll
    for (int db = 0; db < 16; db++) {
        int d = db * 8 + (lane & 3) * 2;
        *(float2*)&R[(size_t)r1 * 128 + d] = make_float2(O[db][0] * inv0, O[db][1] * inv0);
        *(float2*)&R[(size_t)r2 * 128 + d] = make_float2(O[db][2] * inv1, O[db][3] * inv1);
    }
}

// ---------------------------------------------------------------------------
// Kernel 3: out = BN(w4 @ res_view) + x. 512 thr: 16 warps, one m16 each.
// w4 A-fragments loaded directly from global (no W smem).
// ---------------------------------------------------------------------------
#define OS_RH 0            // res: [128 c][128 p] bf16
#define OS_RL 32768
#define OUT_SMEM 65536     // 64 KB

__global__ __launch_bounds__(512, 1) void out_mma(
        const float* __restrict__ x,
        const float* __restrict__ w4,
        const float* __restrict__ gamma,
        const float* __restrict__ beta,
        const float* __restrict__ rmean,
        const float* __restrict__ rvar,
        float* __restrict__ out) {
    extern __shared__ char sm[];
    const uint32_t smb = smem_u32(sm);
    const int tid = threadIdx.x, lane = tid & 31, wid = tid >> 5;
    const int lr = lane & 15, lk = (lane >> 4) * 8;
    const int qr = lane >> 2, qc = (lane & 3) * 2;
    const int m0 = wid * 16;
    const int b = blockIdx.y, p0 = blockIdx.x * 128;
    const float* R = g_res + (size_t)b * CH * HW;

#pragma unroll 2
    for (int i = tid; i < 128 * 32; i += 512) {
        int c = i >> 5, p4 = (i & 31) * 4;
        float4 v = *(const float4*)&R[(size_t)c * HW + p0 + p4];
        uint32_t h0, l0, h1, l1;
        bfsplit2(v.x, v.y, h0, l0);
        bfsplit2(v.z, v.w, h1, l1);
        uint32_t o = off256(c, p4);
        *(uint32_t*)(sm + OS_RH + o) = h0;
        *(uint32_t*)(sm + OS_RL + o) = l0;
        *(uint32_t*)(sm + OS_RH + o + 4) = h1;
        *(uint32_t*)(sm + OS_RL + o + 4) = l1;
    }
    __syncthreads();

    float acc[16][4];
#pragma unroll
    for (int n = 0; n < 16; n++)
#pragma unroll
        for (int k = 0; k < 4; k++) acc[n][k] = 0.f;

    const int ra = (m0 + qr) * CH, rb = (m0 + qr + 8) * CH;
#pragma unroll
    for (int ks = 0; ks < 8; ks++) {
        const int c0 = ks * 16 + qc;
        float2 wv0 = *(const float2*)&w4[ra + c0];
        float2 wv1 = *(const float2*)&w4[rb + c0];
        float2 wv2 = *(const float2*)&w4[ra + c0 + 8];
        float2 wv3 = *(const float2*)&w4[rb + c0 + 8];
        uint32_t ah[4], al[4];
        bfsplit2(wv0.x, wv0.y, ah[0], al[0]);
        bfsplit2(wv1.x, wv1.y, ah[1], al[1]);
        bfsplit2(wv2.x, wv2.y, ah[2], al[2]);
        bfsplit2(wv3.x, wv3.y, ah[3], al[3]);
#pragma unroll
        for (int jg = 0; jg < 8; jg++) {
            uint32_t bh[4], bl[4];
            uint32_t boff = off256(ks * 16 + lr, jg * 16 + lk);
            ldsm4t(bh, smb + OS_RH + boff);
            ldsm4t(bl, smb + OS_RL + boff);
            mma16816(acc[jg*2],   ah, bh[0], bh[1]);
            mma16816(acc[jg*2+1], ah, bh[2], bh[3]);
            mma16816(acc[jg*2],   ah, bl[0], bl[1]);
            mma16816(acc[jg*2+1], ah, bl[2], bl[3]);
            mma16816(acc[jg*2],   al, bh[0], bh[1]);
            mma16816(acc[jg*2+1], al, bh[2], bh[3]);
        }
    }

    int oc1 = m0 + qr, oc2 = oc1 + 8;
    float sc1 = gamma[oc1] * rsqrtf(rvar[oc1] + 1e-5f);
    float sc2 = gamma[oc2] * rsqrtf(rvar[oc2] + 1e-5f);
    float mu1 = rmean[oc1], bt1 = beta[oc1];
    float mu2 = rmean[oc2], bt2 = beta[oc2];
    size_t b1 = (size_t)b * CIN * HW + (size_t)oc1 * HW + p0;
    size_t b2 = (size_t)b * CIN * HW + (size_t)oc2 * HW + p0;
#pragma unroll
    for (int nb = 0; nb < 16; nb++) {
        int col = nb * 8 + qc;
        float2 xv1 = *(const float2*)&x[b1 + col];
        float2 xv2 = *(const float2*)&x[b2 + col];
        *(float2*)&out[b1 + col] = make_float2((acc[nb][0] - mu1) * sc1 + bt1 + xv1.x,
                                               (acc[nb][1] - mu1) * sc1 + bt1 + xv1.y);
        *(float2*)&out[b2 + col] = make_float2((acc[nb][2] - mu2) * sc2 + bt2 + xv2.x,
                                               (acc[nb][3] - mu2) * sc2 + bt2 + xv2.y);
    }
}

// ---------------------------------------------------------------------------
extern "C" void kernel_launch(void* const* d_in, const int* in_sizes, int n_in,
                              void* d_out, int out_size) {
    const float* x     = (const float*)d_in[0];
    const float* w1    = (const float*)d_in[1];
    const float* w2    = (const float*)d_in[2];
    const float* w3    = (const float*)d_in[3];
    const float* w4    = (const float*)d_in[4];
    const float* gamma = (const float*)d_in[5];
    const float* beta  = (const float*)d_in[6];
    const float* rmean = (const float*)d_in[7];
    const float* rvar  = (const float*)d_in[8];
    float* out = (float*)d_out;

    cudaFuncSetAttribute(qkv_mma,
                         cudaFuncAttributeMaxDynamicSharedMemorySize, QKV_SMEM);
    qkv_mma<<<dim3(32, NB), 512, QKV_SMEM>>>(x, w1, w2, w3);

    cudaFuncSetAttribute(flash_mma,
                         cudaFuncAttributeMaxDynamicSharedMemorySize, FLASH_SMEM);
    flash_mma<<<dim3(32, NB), 256, FLASH_SMEM>>>();

    cudaFuncSetAttribute(out_mma,
                         cudaFuncAttributeMaxDynamicSharedMemorySize, OUT_SMEM);
    out_mma<<<dim3(32, NB), 512, OUT_SMEM>>>(x, w4, gamma, beta, rmean, rvar, out);
}

// round 12
// speedup vs baseline: 1.0731x; 1.0044x over previous
#include <cuda_runtime.h>
#include <cuda_bf16.h>
#include <cstdint>

#define HW   4096
#define CIN  256
#define CH   128
#define NB   4

// Scratch (__device__ globals; allocation-free rule). ALL natural [f][p] layouts.
__device__ __nv_bfloat16 g_qh[NB*CH*HW], g_ql[NB*CH*HW];  // Q viewed [i=4096][c=128]
__device__ __nv_bfloat16 g_kh[NB*CH*HW], g_kl[NB*CH*HW];  // K natural [c=128][j=4096]
__device__ __nv_bfloat16 g_vh[NB*CH*HW], g_vl[NB*CH*HW];  // V viewed [j=4096][d=128]
__device__ float g_res[NB*CH*HW];                          // res [i][d] flat = [128][4096] view

// ---- bf16 hi/lo split ------------------------------------------------------
__device__ __forceinline__ uint32_t b2u(__nv_bfloat162 v) {
    return *reinterpret_cast<uint32_t*>(&v);
}
__device__ __forceinline__ void bfsplit2(float a, float b,
                                         uint32_t& hi, uint32_t& lo) {
    __nv_bfloat162 h = __floats2bfloat162_rn(a, b);
    float ra = a - __low2float(h);
    float rb = b - __high2float(h);
    __nv_bfloat162 l = __floats2bfloat162_rn(ra, rb);
    hi = b2u(h); lo = b2u(l);
}

__device__ __forceinline__ uint32_t smem_u32(const void* p) {
    uint32_t a;
    asm("{ .reg .u64 t; cvta.to.shared.u64 t, %1; cvt.u32.u64 %0, t; }"
        : "=r"(a) : "l"(p));
    return a;
}

// ---- mma.sync / ldmatrix / cp.async wrappers (portable sm_80+) -------------
__device__ __forceinline__ void ldsm4(uint32_t* r, uint32_t addr) {
    asm volatile("ldmatrix.sync.aligned.m8n8.x4.shared.b16 {%0,%1,%2,%3}, [%4];"
                 : "=r"(r[0]), "=r"(r[1]), "=r"(r[2]), "=r"(r[3]) : "r"(addr));
}
__device__ __forceinline__ void ldsm4t(uint32_t* r, uint32_t addr) {
    asm volatile("ldmatrix.sync.aligned.m8n8.x4.trans.shared.b16 {%0,%1,%2,%3}, [%4];"
                 : "=r"(r[0]), "=r"(r[1]), "=r"(r[2]), "=r"(r[3]) : "r"(addr));
}
__device__ __forceinline__ void mma16816(float* d, const uint32_t* a,
                                         uint32_t b0, uint32_t b1) {
    asm volatile(
        "mma.sync.aligned.m16n8k16.row.col.f32.bf16.bf16.f32 "
        "{%0,%1,%2,%3}, {%4,%5,%6,%7}, {%8,%9}, {%0,%1,%2,%3};"
        : "+f"(d[0]), "+f"(d[1]), "+f"(d[2]), "+f"(d[3])
        : "r"(a[0]), "r"(a[1]), "r"(a[2]), "r"(a[3]), "r"(b0), "r"(b1));
}
__device__ __forceinline__ void cpasync16(uint32_t dst, const void* src) {
    asm volatile("cp.async.cg.shared.global [%0], [%1], 16;" :: "r"(dst), "l"(src));
}
#define CP_COMMIT() asm volatile("cp.async.commit_group;" ::: "memory")
#define CP_WAIT1()  asm volatile("cp.async.wait_group 1;" ::: "memory")
#define CP_WAIT0()  asm volatile("cp.async.wait_group 0;" ::: "memory")

// ---- swizzled smem offsets (16B chunk XOR by row) --------------------------
__device__ __forceinline__ uint32_t off256(int r, int c) {  // 256B rows, 128 bf16 cols
    return (uint32_t)(r * 256 + ((((c >> 3) ^ r) & 7) << 4) + ((c >> 3) & ~7) * 16 + (c & 7) * 2);
}
__device__ __forceinline__ uint32_t off128b(int r, int c) { // 128B rows, 64 bf16 cols
    return (uint32_t)(r * 128 + (((c >> 3) ^ (r & 7)) << 4) + (c & 7) * 2);
}

// ---------------------------------------------------------------------------
// Kernel 1: QKV via mma.sync bf16x3 (unchanged from round 11).
// ---------------------------------------------------------------------------
#define QS_XH 0            // X: [256 k][128 n] bf16
#define QS_XL 65536
#define QKV_SMEM 131072    // 128 KB

__global__ __launch_bounds__(512, 1) void qkv_mma(
        const float* __restrict__ x,
        const float* __restrict__ w1,
        const float* __restrict__ w2,
        const float* __restrict__ w3) {
    extern __shared__ char sm[];
    const uint32_t smb = smem_u32(sm);
    const int tid = threadIdx.x, lane = tid & 31, wid = tid >> 5;
    const int lr = lane & 15, lk = (lane >> 4) * 8;
    const int qr = lane >> 2, qc = (lane & 3) * 2;
    const int wm = wid & 7, wn = wid >> 3;
    const int m0 = wm * 16;
    const int b = blockIdx.y, p0 = blockIdx.x * 128;
    const float* X = x + (size_t)b * CIN * HW;
    const size_t bo = (size_t)b * CH * HW;

#pragma unroll 4
    for (int i = tid; i < 256 * 32; i += 512) {
        int r = i >> 5, c4 = (i & 31) * 4;
        float4 v = *(const float4*)&X[(size_t)r * HW + p0 + c4];
        uint32_t h0, l0, h1, l1;
        bfsplit2(v.x, v.y, h0, l0);
        bfsplit2(v.z, v.w, h1, l1);
        uint32_t o = off256(r, c4);
        *(uint32_t*)(sm + QS_XH + o) = h0;
        *(uint32_t*)(sm + QS_XL + o) = l0;
        *(uint32_t*)(sm + QS_XH + o + 4) = h1;
        *(uint32_t*)(sm + QS_XL + o + 4) = l1;
    }
    __syncthreads();

    const int ra = (m0 + qr) * CIN, rb = (m0 + qr + 8) * CIN;

#pragma unroll 1
    for (int s = 0; s < 3; s++) {
        const float* W = (s == 0) ? w1 : (s == 1) ? w2 : w3;
        __nv_bfloat16* OH = ((s == 0) ? g_qh : (s == 1) ? g_kh : g_vh) + bo;
        __nv_bfloat16* OL = ((s == 0) ? g_ql : (s == 1) ? g_kl : g_vl) + bo;

        float acc[8][4];
#pragma unroll
        for (int n = 0; n < 8; n++)
#pragma unroll
            for (int k = 0; k < 4; k++) acc[n][k] = 0.f;

#pragma unroll
        for (int ks = 0; ks < 16; ks++) {
            const int c0 = ks * 16 + qc;
            float2 wv0 = *(const float2*)&W[ra + c0];
            float2 wv1 = *(const float2*)&W[rb + c0];
            float2 wv2 = *(const float2*)&W[ra + c0 + 8];
            float2 wv3 = *(const float2*)&W[rb + c0 + 8];
            uint32_t ah[4], al[4];
            bfsplit2(wv0.x, wv0.y, ah[0], al[0]);
            bfsplit2(wv1.x, wv1.y, ah[1], al[1]);
            bfsplit2(wv2.x, wv2.y, ah[2], al[2]);
            bfsplit2(wv3.x, wv3.y, ah[3], al[3]);
#pragma unroll
            for (int jg = 0; jg < 4; jg++) {
                uint32_t bh[4], bl[4];
                uint32_t boff = off256(ks * 16 + lr, wn * 64 + jg * 16 + lk);
                ldsm4t(bh, smb + QS_XH + boff);
                ldsm4t(bl, smb + QS_XL + boff);
                mma16816(acc[jg*2],   ah, bh[0], bh[1]);
                mma16816(acc[jg*2+1], ah, bh[2], bh[3]);
                mma16816(acc[jg*2],   ah, bl[0], bl[1]);
                mma16816(acc[jg*2+1], ah, bl[2], bl[3]);
                mma16816(acc[jg*2],   al, bh[0], bh[1]);
                mma16816(acc[jg*2+1], al, bh[2], bh[3]);
            }
        }

        int f1 = m0 + qr;
#pragma unroll
        for (int nb = 0; nb < 8; nb++) {
            int col = p0 + wn * 64 + nb * 8 + qc;
            uint32_t h0, l0, h1, l1;
            bfsplit2(acc[nb][0], acc[nb][1], h0, l0);
            bfsplit2(acc[nb][2], acc[nb][3], h1, l1);
            *(uint32_t*)&OH[(size_t)f1 * HW + col] = h0;
            *(uint32_t*)&OL[(size_t)f1 * HW + col] = l0;
            *(uint32_t*)&OH[(size_t)(f1 + 8) * HW + col] = h1;
            *(uint32_t*)&OL[(size_t)(f1 + 8) * HW + col] = l1;
        }
    }
}

// ---------------------------------------------------------------------------
// Kernel 2: flash attention. Q fragments in registers (direct global loads),
// 3-stage cp.async pipeline, softmax interleaved with PV per k-block.
// 256 thr, 8 warps m16 each. BM=128, BN=64, D=128.
// ---------------------------------------------------------------------------
#define KHO 0
#define KLO 16384
#define VHO 32768
#define VLO 49152
#define STAGE 65536
#define FLASH_SMEM (3 * STAGE)   // 192 KB

__global__ __launch_bounds__(256, 1) void flash_mma() {
    extern __shared__ char sm[];
    const uint32_t smb = smem_u32(sm);
    const int tid = threadIdx.x, lane = tid & 31, wid = tid >> 5;
    const int lr = lane & 15, lk = (lane >> 4) * 8;
    const int qr = lane >> 2, qc = (lane & 3) * 2;
    const int m0 = wid * 16;
    const int b = blockIdx.y, i0 = blockIdx.x * 128;
    const size_t bo = (size_t)b * CH * HW;
    const __nv_bfloat16 *Qh = g_qh + bo, *Ql = g_ql + bo;
    const __nv_bfloat16 *Kh = g_kh + bo, *Kl = g_kl + bo;
    const __nv_bfloat16 *Vh = g_vh + bo, *Vl = g_vl + bo;

    auto prefetch = [&](int tt, int stg) {
        const int j0 = tt * 64;
        const uint32_t base = smb + (uint32_t)stg * STAGE;
#pragma unroll
        for (int q = 0; q < 4; q++) {
            int i = tid + q * 256;
            {
                int c = i >> 3, j8 = (i & 7) * 8;
                uint32_t o = off128b(c, j8);
                cpasync16(base + KHO + o, Kh + (size_t)c * HW + j0 + j8);
                cpasync16(base + KLO + o, Kl + (size_t)c * HW + j0 + j8);
            }
            {
                int j = i >> 4, d8 = (i & 15) * 8;
                uint32_t o = off256(j, d8);
                cpasync16(base + VHO + o, Vh + (size_t)(j0 + j) * 128 + d8);
                cpasync16(base + VLO + o, Vl + (size_t)(j0 + j) * 128 + d8);
            }
        }
    };

    prefetch(0, 0); CP_COMMIT();
    prefetch(1, 1); CP_COMMIT();

    // ---- Q fragments: direct global loads, persistent across all tiles ----
    uint32_t qfh[8][4], qfl[8][4];
    {
        const size_t r0g = (size_t)(i0 + m0 + qr) * 128;
        const size_t r1g = r0g + 8 * 128;
#pragma unroll
        for (int ks = 0; ks < 8; ks++) {
            int c = ks * 16 + qc;
            qfh[ks][0] = *(const uint32_t*)&Qh[r0g + c];
            qfh[ks][1] = *(const uint32_t*)&Qh[r1g + c];
            qfh[ks][2] = *(const uint32_t*)&Qh[r0g + c + 8];
            qfh[ks][3] = *(const uint32_t*)&Qh[r1g + c + 8];
            qfl[ks][0] = *(const uint32_t*)&Ql[r0g + c];
            qfl[ks][1] = *(const uint32_t*)&Ql[r1g + c];
            qfl[ks][2] = *(const uint32_t*)&Ql[r0g + c + 8];
            qfl[ks][3] = *(const uint32_t*)&Ql[r1g + c + 8];
        }
    }

    float O[16][4];
#pragma unroll
    for (int d = 0; d < 16; d++)
#pragma unroll
        for (int k = 0; k < 4; k++) O[d][k] = 0.f;
    float ls0 = 0.f, ls1 = 0.f;

    for (int t = 0; t < 64; t++) {
        if (t >= 62) CP_WAIT0(); else CP_WAIT1();
        __syncthreads();   // stage t visible to all; all done reading stage (t-1)%3
        if (t + 2 < 64) { prefetch(t + 2, (t + 2) % 3); CP_COMMIT(); }
        const uint32_t kb = smb + (uint32_t)(t % 3) * STAGE;

        // ---- S = Q K^T (bf16x3), Q from registers ----
        float S[8][4];
#pragma unroll
        for (int n = 0; n < 8; n++)
#pragma unroll
            for (int k = 0; k < 4; k++) S[n][k] = 0.f;

#pragma unroll
        for (int ks = 0; ks < 8; ks++) {
#pragma unroll
            for (int jg = 0; jg < 4; jg++) {
                uint32_t khf[4], klf[4];
                uint32_t koff = off128b(ks * 16 + lr, jg * 16 + lk);
                ldsm4t(khf, kb + KHO + koff);
                ldsm4t(klf, kb + KLO + koff);
                mma16816(S[jg*2],   qfh[ks], khf[0], khf[1]);
                mma16816(S[jg*2+1], qfh[ks], khf[2], khf[3]);
                mma16816(S[jg*2],   qfh[ks], klf[0], klf[1]);
                mma16816(S[jg*2+1], qfh[ks], klf[2], klf[3]);
                mma16816(S[jg*2],   qfl[ks], khf[0], khf[1]);
                mma16816(S[jg*2+1], qfl[ks], khf[2], khf[3]);
            }
        }

        // ---- softmax interleaved with PV per k-block ----
        float a0 = 0.f, a1 = 0.f;
#pragma unroll
        for (int kbi = 0; kbi < 4; kbi++) {
            uint32_t pHk[4], pLk[4];
            {
                float e0 = __expf(S[2*kbi][0]), e1 = __expf(S[2*kbi][1]);
                float e2 = __expf(S[2*kbi][2]), e3 = __expf(S[2*kbi][3]);
                a0 += e0 + e1; a1 += e2 + e3;
                bfsplit2(e0, e1, pHk[0], pLk[0]);
                bfsplit2(e2, e3, pHk[1], pLk[1]);
            }
            {
                float e0 = __expf(S[2*kbi+1][0]), e1 = __expf(S[2*kbi+1][1]);
                float e2 = __expf(S[2*kbi+1][2]), e3 = __expf(S[2*kbi+1][3]);
                a0 += e0 + e1; a1 += e2 + e3;
                bfsplit2(e0, e1, pHk[2], pLk[2]);
                bfsplit2(e2, e3, pHk[3], pLk[3]);
            }
#pragma unroll
            for (int dg = 0; dg < 8; dg++) {
                uint32_t vhf[4], vlf[4];
                uint32_t voff = off256(kbi * 16 + lr, dg * 16 + lk);
                ldsm4t(vhf, kb + VHO + voff);
                ldsm4t(vlf, kb + VLO + voff);
                mma16816(O[dg*2],   pHk, vhf[0], vhf[1]);
                mma16816(O[dg*2+1], pHk, vhf[2], vhf[3]);
                mma16816(O[dg*2],   pHk, vlf[0], vlf[1]);
                mma16816(O[dg*2+1], pHk, vlf[2], vlf[3]);
                mma16816(O[dg*2],   pLk, vhf[0], vhf[1]);
                mma16816(O[dg*2+1], pLk, vhf[2], vhf[3]);
            }
        }
        a0 += __shfl_xor_sync(0xffffffffu, a0, 1);
        a0 += __shfl_xor_sync(0xffffffffu, a0, 2);
        a1 += __shfl_xor_sync(0xffffffffu, a1, 1);
        a1 += __shfl_xor_sync(0xffffffffu, a1, 2);
        ls0 += a0; ls1 += a1;
    }

    float inv0 = 1.0f / ls0, inv1 = 1.0f / ls1;
    int r1 = i0 + m0 + qr, r2 = r1 + 8;
    float* R = g_res + bo;
#pragma unroll
    for (int db = 0; db < 16; db++) {
        int d = db * 8 + qc;
        *(float2*)&R[(size_t)r1 * 128 + d] = make_float2(O[db][0] * inv0, O[db][1] * inv0);
        *(float2*)&R[(size_t)r2 * 128 + d] = make_float2(O[db][2] * inv1, O[db][3] * inv1);
    }
}

// ---------------------------------------------------------------------------
// Kernel 3: out = BN(w4 @ res_view) + x (unchanged from round 11).
// ---------------------------------------------------------------------------
#define OS_RH 0
#define OS_RL 32768
#define OUT_SMEM 65536     // 64 KB

__global__ __launch_bounds__(512, 1) void out_mma(
        const float* __restrict__ x,
        const float* __restrict__ w4,
        const float* __restrict__ gamma,
        const float* __restrict__ beta,
        const float* __restrict__ rmean,
        const float* __restrict__ rvar,
        float* __restrict__ out) {
    extern __shared__ char sm[];
    const uint32_t smb = smem_u32(sm);
    const int tid = threadIdx.x, lane = tid & 31, wid = tid >> 5;
    const int lr = lane & 15, lk = (lane >> 4) * 8;
    const int qr = lane >> 2, qc = (lane & 3) * 2;
    const int m0 = wid * 16;
    const int b = blockIdx.y, p0 = blockIdx.x * 128;
    const float* R = g_res + (size_t)b * CH * HW;

#pragma unroll 2
    for (int i = tid; i < 128 * 32; i += 512) {
        int c = i >> 5, p4 = (i & 31) * 4;
        float4 v = *(const float4*)&R[(size_t)c * HW + p0 + p4];
        uint32_t h0, l0, h1, l1;
        bfsplit2(v.x, v.y, h0, l0);
        bfsplit2(v.z, v.w, h1, l1);
        uint32_t o = off256(c, p4);
        *(uint32_t*)(sm + OS_RH + o) = h0;
        *(uint32_t*)(sm + OS_RL + o) = l0;
        *(uint32_t*)(sm + OS_RH + o + 4) = h1;
        *(uint32_t*)(sm + OS_RL + o + 4) = l1;
    }
    __syncthreads();

    float acc[16][4];
#pragma unroll
    for (int n = 0; n < 16; n++)
#pragma unroll
        for (int k = 0; k < 4; k++) acc[n][k] = 0.f;

    const int ra = (m0 + qr) * CH, rb = (m0 + qr + 8) * CH;
#pragma unroll
    for (int ks = 0; ks < 8; ks++) {
        const int c0 = ks * 16 + qc;
        float2 wv0 = *(const float2*)&w4[ra + c0];
        float2 wv1 = *(const float2*)&w4[rb + c0];
        float2 wv2 = *(const float2*)&w4[ra + c0 + 8];
        float2 wv3 = *(const float2*)&w4[rb + c0 + 8];
        uint32_t ah[4], al[4];
        bfsplit2(wv0.x, wv0.y, ah[0], al[0]);
        bfsplit2(wv1.x, wv1.y, ah[1], al[1]);
        bfsplit2(wv2.x, wv2.y, ah[2], al[2]);
        bfsplit2(wv3.x, wv3.y, ah[3], al[3]);
#pragma unroll
        for (int jg = 0; jg < 8; jg++) {
            uint32_t bh[4], bl[4];
            uint32_t boff = off256(ks * 16 + lr, jg * 16 + lk);
            ldsm4t(bh, smb + OS_RH + boff);
            ldsm4t(bl, smb + OS_RL + boff);
            mma16816(acc[jg*2],   ah, bh[0], bh[1]);
            mma16816(acc[jg*2+1], ah, bh[2], bh[3]);
            mma16816(acc[jg*2],   ah, bl[0], bl[1]);
            mma16816(acc[jg*2+1], ah, bl[2], bl[3]);
            mma16816(acc[jg*2],   al, bh[0], bh[1]);
            mma16816(acc[jg*2+1], al, bh[2], bh[3]);
        }
    }

    int oc1 = m0 + qr, oc2 = oc1 + 8;
    float sc1 = gamma[oc1] * rsqrtf(rvar[oc1] + 1e-5f);
    float sc2 = gamma[oc2] * rsqrtf(rvar[oc2] + 1e-5f);
    float mu1 = rmean[oc1], bt1 = beta[oc1];
    float mu2 = rmean[oc2], bt2 = beta[oc2];
    size_t b1 = (size_t)b * CIN * HW + (size_t)oc1 * HW + p0;
    size_t b2 = (size_t)b * CIN * HW + (size_t)oc2 * HW + p0;
#pragma unroll
    for (int nb = 0; nb < 16; nb++) {
        int col = nb * 8 + qc;
        float2 xv1 = *(const float2*)&x[b1 + col];
        float2 xv2 = *(const float2*)&x[b2 + col];
        *(float2*)&out[b1 + col] = make_float2((acc[nb][0] - mu1) * sc1 + bt1 + xv1.x,
                                               (acc[nb][1] - mu1) * sc1 + bt1 + xv1.y);
        *(float2*)&out[b2 + col] = make_float2((acc[nb][2] - mu2) * sc2 + bt2 + xv2.x,
                                               (acc[nb][3] - mu2) * sc2 + bt2 + xv2.y);
    }
}

// ---------------------------------------------------------------------------
extern "C" void kernel_launch(void* const* d_in, const int* in_sizes, int n_in,
                              void* d_out, int out_size) {
    const float* x     = (const float*)d_in[0];
    const float* w1    = (const float*)d_in[1];
    const float* w2    = (const float*)d_in[2];
    const float* w3    = (const float*)d_in[3];
    const float* w4    = (const float*)d_in[4];
    const float* gamma = (const float*)d_in[5];
    const float* beta  = (const float*)d_in[6];
    const float* rmean = (const float*)d_in[7];
    const float* rvar  = (const float*)d_in[8];
    float* out = (float*)d_out;

    cudaFuncSetAttribute(qkv_mma,
                         cudaFuncAttributeMaxDynamicSharedMemorySize, QKV_SMEM);
    qkv_mma<<<dim3(32, NB), 512, QKV_SMEM>>>(x, w1, w2, w3);

    cudaFuncSetAttribute(flash_mma,
                         cudaFuncAttributeMaxDynamicSharedMemorySize, FLASH_SMEM);
    flash_mma<<<dim3(32, NB), 256, FLASH_SMEM>>>();

    cudaFuncSetAttribute(out_mma,
                         cudaFuncAttributeMaxDynamicSharedMemorySize, OUT_SMEM);
    out_mma<<<dim3(32, NB), 512, OUT_SMEM>>>(x, w4, gamma, beta, rmean, rvar, out);
}